// round 16
// baseline (speedup 1.0000x reference)
#include <cuda_runtime.h>

#define T_LEN   750
#define CH      4
#define THREADS 192          // 192*4 = 768 >= 750; 6 warps
#define NSLOT   64
#define SLOT_STRIDE 32       // 128B stride

__device__ float        g_slots[NSLOT * SLOT_STRIDE];   // zero-init at load
__device__ unsigned int g_count;                        // zero-init at load

// Degree-4 Taylor of exp(-t/2) about t=0.5, valid t in [0,1], |err| < 8.5e-6.
// p(t) = c0 + c1 t + c2 t^2 + c3 t^3 + c4 t^4  (Horner, 4 FFMA, zero MUFU)
#define PC4  0.00202813f
#define PC3 (-0.02028130f)
#define PC2  0.12472984f
#define PC1 (-0.49993338f)
#define PC0  0.99999339f

static __device__ __forceinline__ float exp_half_poly(float t) {
    // t = |d| in [0,1)
    float p = fmaf(PC4, t, PC3);
    p = fmaf(p, t, PC2);
    p = fmaf(p, t, PC1);
    p = fmaf(p, t, PC0);
    return p;
}

__global__ __launch_bounds__(THREADS)
void ae_loss_kernel(const float* __restrict__ a0,
                    const float* __restrict__ a2,
                    float* __restrict__ out,
                    int B) {
    __shared__ float rw[THREADS / 32];
    __shared__ float rn[THREADS / 32];
    __shared__ bool  is_last;

    const int b   = blockIdx.x;
    const int tid = threadIdx.x;
    const float* __restrict__ g0 = a0 + (size_t)b * T_LEN;
    const float* __restrict__ g2 = a2 + (size_t)b * T_LEN;

    const int i_base = tid * CH;
    float acc2a = 0.0f, acc2b = 0.0f;  // pair distance 1..2 / 3..4 (x2)
    float acc1  = 0.0f;                // pair distance 5..6        (x1)
    float nsq   = 0.0f;                // sum (a0-a2)^2

    if (i_base < T_LEN) {
        float v0[10], v2[10];
        if (i_base + 9 <= T_LEN - 1) {
            const float2* p0 = reinterpret_cast<const float2*>(g0 + i_base);
            const float2* p2 = reinterpret_cast<const float2*>(g2 + i_base);
#pragma unroll
            for (int q = 0; q < 5; q++) {
                float2 t0 = p0[q], t2 = p2[q];
                v0[2*q] = t0.x; v0[2*q+1] = t0.y;
                v2[2*q] = t2.x; v2[2*q+1] = t2.y;
            }
            // Fast path: all 4 outputs and all partners in-range
#pragma unroll
            for (int c = 0; c < CH; c++) {
                const float x0 = v0[c], x2 = v2[c];
                const float d = x0 - x2;
                nsq = fmaf(d, d, nsq);
#pragma unroll
                for (int k = 1; k <= 6; k++) {
                    const float e = exp_half_poly(fabsf(x0 - v0[c+k]));
                    const float t = e * fabsf(x2 - v2[c+k]);
                    if      (k <= 2) acc2a += t;
                    else if (k <= 4) acc2b += t;
                    else             acc1  += t;
                }
            }
        } else {
            // Tail path (threads 186..191): clamped scalar loads + masked terms
#pragma unroll
            for (int m = 0; m < 10; m++) {
                int idx = i_base + m;
                idx = idx > T_LEN - 1 ? T_LEN - 1 : idx;
                v0[m] = g0[idx];
                v2[m] = g2[idx];
            }
#pragma unroll
            for (int c = 0; c < CH; c++) {
                const int i = i_base + c;
                if (i < T_LEN) {
                    const float x0 = v0[c], x2 = v2[c];
                    const float d = x0 - x2;
                    nsq = fmaf(d, d, nsq);
#pragma unroll
                    for (int k = 1; k <= 6; k++) {
                        if (i + k < T_LEN) {
                            const float e = exp_half_poly(fabsf(x0 - v0[c+k]));
                            const float t = e * fabsf(x2 - v2[c+k]);
                            if      (k <= 2) acc2a += t;
                            else if (k <= 4) acc2b += t;
                            else             acc1  += t;
                        }
                    }
                }
            }
        }
    }

    float wsum = fmaf(2.0f, acc2a + acc2b, acc1);

    // Clamped-boundary extras (8 terms; replicates reference padding):
    //   left : u=1..5     -> (6-u)   * term(u, 0)
    //   right: u=746..748 -> (u-745) * term(u, 749)
    if (tid < 8) {
        int u, p; float mult;
        if (tid < 5) { u = tid + 1;   p = 0;         mult = (float)(5 - tid); }
        else         { u = 741 + tid; p = T_LEN - 1; mult = (float)(tid - 4); }
        const float e = exp_half_poly(fabsf(g0[u] - g0[p]));
        wsum = fmaf(mult * e, fabsf(g2[u] - g2[p]), wsum);
    }

    // Block reduction (6 warps)
#pragma unroll
    for (int o = 16; o > 0; o >>= 1) {
        wsum += __shfl_down_sync(0xFFFFFFFFu, wsum, o);
        nsq  += __shfl_down_sync(0xFFFFFFFFu, nsq,  o);
    }
    const int warp = tid >> 5, lane = tid & 31;
    if (lane == 0) { rw[warp] = wsum; rn[warp] = nsq; }
    __syncthreads();

    if (tid == 0) {
        float w = rw[0], n = rn[0];
#pragma unroll
        for (int q = 1; q < THREADS / 32; q++) { w += rw[q]; n += rn[q]; }
        atomicAdd(&g_slots[(b & (NSLOT - 1)) * SLOT_STRIDE], w + 0.1f * sqrtf(n));
        __threadfence();
        unsigned int prev = atomicAdd(&g_count, 1u);
        is_last = (prev == (unsigned int)(B - 1));
    }
    __syncthreads();

    // Last block: reduce slots, write result, reset state for next replay.
    if (is_last) {
        float v = 0.0f;
        if (tid < NSLOT)
            v = atomicAdd(&g_slots[tid * SLOT_STRIDE], 0.0f);  // L2-coherent read
#pragma unroll
        for (int o = 16; o > 0; o >>= 1)
            v += __shfl_down_sync(0xFFFFFFFFu, v, o);
        if (lane == 0 && warp < 2) rw[warp] = v;
        __syncthreads();
        if (tid == 0) {
            out[0] = rw[0] + rw[1];
            g_count = 0u;
        }
        __syncthreads();
        if (tid < NSLOT) g_slots[tid * SLOT_STRIDE] = 0.0f;
    }
}

extern "C" void kernel_launch(void* const* d_in, const int* in_sizes, int n_in,
                              void* d_out, int out_size) {
    const float* a0 = (const float*)d_in[0];
    const float* a2 = (const float*)d_in[1];
    float* out = (float*)d_out;

    const int B = in_sizes[0] / T_LEN;   // 4096

    ae_loss_kernel<<<B, THREADS>>>(a0, a2, out, B);
}

// round 17
// speedup vs baseline: 1.0210x; 1.0210x over previous
#include <cuda_runtime.h>

#define T_LEN   750
#define CH      4
#define THREADS 192          // 192*4 = 768 >= 750; 6 warps
#define NSLOT   64
#define SLOT_STRIDE 32       // 128B stride

// exp(-x/2) = exp2(-x * 0.5*log2(e))
#define NEG_HALF_LOG2E (-0.7213475204444817f)

__device__ float        g_slots[NSLOT * SLOT_STRIDE];   // zero-init at load
__device__ unsigned int g_count;                        // zero-init at load

static __device__ __forceinline__ float ex2_approx(float x) {
    float r; asm("ex2.approx.ftz.f32 %0, %1;" : "=f"(r) : "f"(x)); return r;
}

__global__ __launch_bounds__(THREADS)
void ae_loss_kernel(const float* __restrict__ a0,
                    const float* __restrict__ a2,
                    float* __restrict__ out,
                    int B) {
    __shared__ float rw[THREADS / 32];
    __shared__ float rn[THREADS / 32];
    __shared__ bool  is_last;

    const int b   = blockIdx.x;
    const int tid = threadIdx.x;
    const float* __restrict__ g0 = a0 + (size_t)b * T_LEN;
    const float* __restrict__ g2 = a2 + (size_t)b * T_LEN;

    const int i_base = tid * CH;
    float acc2a = 0.0f, acc2b = 0.0f;  // pair distance 1..2 / 3..4 (x2)
    float acc1  = 0.0f;                // pair distance 5..6        (x1)
    float nsq   = 0.0f;                // sum (a0-a2)^2

    if (i_base < T_LEN) {
        if (i_base + 11 <= T_LEN - 1) {
            // Fast path (threads 0..184): 3x LDG.128 per array.
            // i_base*4 bytes is 16B-aligned and rows start at 16B-multiples?
            // Row byte offset = b*3000: 3000 % 16 = 8 -> NOT always 16B aligned.
            // But (g0 + i_base) alignment = (b*3000 + i_base*4) % 16: i_base*4
            // is a multiple of 16, so alignment is 8 for odd b. Use float2-based
            // float4 emulation only when aligned; simpler: use 16B loads only
            // when (b & 1) == 0 is NOT knowable per-thread at compile time, so
            // instead do 6x LDG.64 covering 12 floats (still fewer than the
            // previous per-element path and always 8B-aligned).
            float v0[12], v2[12];
            const float2* p0 = reinterpret_cast<const float2*>(g0 + i_base);
            const float2* p2 = reinterpret_cast<const float2*>(g2 + i_base);
#pragma unroll
            for (int q = 0; q < 6; q++) {
                float2 t0 = p0[q], t2 = p2[q];
                v0[2*q] = t0.x; v0[2*q+1] = t0.y;
                v2[2*q] = t2.x; v2[2*q+1] = t2.y;
            }
            // 4 outputs x 6 symmetric partners, all in-range
#pragma unroll
            for (int c = 0; c < CH; c++) {
                const float x0 = v0[c], x2 = v2[c];
                const float d = x0 - x2;
                nsq = fmaf(d, d, nsq);
#pragma unroll
                for (int k = 1; k <= 6; k++) {
                    const float e = ex2_approx(fabsf(x0 - v0[c+k]) * NEG_HALF_LOG2E);
                    const float t = e * fabsf(x2 - v2[c+k]);
                    if      (k <= 2) acc2a += t;
                    else if (k <= 4) acc2b += t;
                    else             acc1  += t;
                }
            }
        } else {
            // Tail path (threads 185..191): clamped scalar loads + masked terms
            float v0[10], v2[10];
#pragma unroll
            for (int m = 0; m < 10; m++) {
                int idx = i_base + m;
                idx = idx > T_LEN - 1 ? T_LEN - 1 : idx;
                v0[m] = g0[idx];
                v2[m] = g2[idx];
            }
#pragma unroll
            for (int c = 0; c < CH; c++) {
                const int i = i_base + c;
                if (i < T_LEN) {
                    const float x0 = v0[c], x2 = v2[c];
                    const float d = x0 - x2;
                    nsq = fmaf(d, d, nsq);
#pragma unroll
                    for (int k = 1; k <= 6; k++) {
                        if (i + k < T_LEN) {
                            const float e = ex2_approx(fabsf(x0 - v0[c+k]) * NEG_HALF_LOG2E);
                            const float t = e * fabsf(x2 - v2[c+k]);
                            if      (k <= 2) acc2a += t;
                            else if (k <= 4) acc2b += t;
                            else             acc1  += t;
                        }
                    }
                }
            }
        }
    }

    float wsum = fmaf(2.0f, acc2a + acc2b, acc1);

    // Clamped-boundary extras (8 terms; replicates reference padding):
    //   left : u=1..5     -> (6-u)   * term(u, 0)
    //   right: u=746..748 -> (u-745) * term(u, 749)
    if (tid < 8) {
        int u, p; float mult;
        if (tid < 5) { u = tid + 1;   p = 0;         mult = (float)(5 - tid); }
        else         { u = 741 + tid; p = T_LEN - 1; mult = (float)(tid - 4); }
        const float e = ex2_approx(fabsf(g0[u] - g0[p]) * NEG_HALF_LOG2E);
        wsum = fmaf(mult * e, fabsf(g2[u] - g2[p]), wsum);
    }

    // Block reduction (6 warps)
#pragma unroll
    for (int o = 16; o > 0; o >>= 1) {
        wsum += __shfl_down_sync(0xFFFFFFFFu, wsum, o);
        nsq  += __shfl_down_sync(0xFFFFFFFFu, nsq,  o);
    }
    const int warp = tid >> 5, lane = tid & 31;
    if (lane == 0) { rw[warp] = wsum; rn[warp] = nsq; }
    __syncthreads();

    if (tid == 0) {
        float w = rw[0], n = rn[0];
#pragma unroll
        for (int q = 1; q < THREADS / 32; q++) { w += rw[q]; n += rn[q]; }
        atomicAdd(&g_slots[(b & (NSLOT - 1)) * SLOT_STRIDE], w + 0.1f * sqrtf(n));
        __threadfence();
        unsigned int prev = atomicAdd(&g_count, 1u);
        is_last = (prev == (unsigned int)(B - 1));
    }
    __syncthreads();

    // Last block: reduce slots, write result, reset state for next replay.
    if (is_last) {
        float v = 0.0f;
        if (tid < NSLOT)
            v = atomicAdd(&g_slots[tid * SLOT_STRIDE], 0.0f);  // L2-coherent read
#pragma unroll
        for (int o = 16; o > 0; o >>= 1)
            v += __shfl_down_sync(0xFFFFFFFFu, v, o);
        if (lane == 0 && warp < 2) rw[warp] = v;
        __syncthreads();
        if (tid == 0) {
            out[0] = rw[0] + rw[1];
            g_count = 0u;
        }
        __syncthreads();
        if (tid < NSLOT) g_slots[tid * SLOT_STRIDE] = 0.0f;
    }
}

extern "C" void kernel_launch(void* const* d_in, const int* in_sizes, int n_in,
                              void* d_out, int out_size) {
    const float* a0 = (const float*)d_in[0];
    const float* a2 = (const float*)d_in[1];
    float* out = (float*)d_out;

    const int B = in_sizes[0] / T_LEN;   // 4096

    ae_loss_kernel<<<B, THREADS>>>(a0, a2, out, B);
}